// round 8
// baseline (speedup 1.0000x reference)
#include <cuda_runtime.h>

// Hand_Input_Sorter: per-frame conditional 65<->65 half-swap of [*,130] fp32.
// v8: process PAIRS of frames (260 floats = 65 float4, 16B-aligned) with fully
// aligned LDG.128/STG.128. The +-65-float swap permutation is realized in
// registers via warp shuffles. Lane l holds A=word l (elems 4l..4l+3),
// B=word l+32 (elems 128+4l..131+4l), C=word 64 (elems 256..259, uniform).

static constexpr int FRAME_LEN = 130;
static constexpr unsigned FULL = 0xFFFFFFFFu;

__device__ __forceinline__ bool compute_skip(float h0, float p0, float h1, float p1)
{
    bool nan0 = isnan(h0);
    bool nan1 = isnan(h1);
    bool skip = (h1 > h0);                 // false if either NaN (IEEE, matches jnp)
    skip |= (nan0 && nan1);                // both missing
    skip |= (nan0 && (h1 == 1.0f));        // only hand1, labeled right
    skip |= (nan1 && (h0 == 0.0f));        // only hand0, labeled left
    if (!nan0 && !nan1 && (h0 == h1)) {
        skip |= ((h0 == 0.0f) && (p0 > p1));
        skip |= ((h0 == 1.0f) && (p0 < p1));
    }
    return skip;
}

// Single-frame float2 fallback (odd n_frames tail only; never taken in bench).
__device__ __forceinline__ void tail_frame(const float* __restrict__ X,
                                           float* __restrict__ out,
                                           int frame, int lane)
{
    const float2* __restrict__ i2 = (const float2*)(X + (size_t)frame * FRAME_LEN);
    float2 a = __ldg(&i2[lane]);
    float2 b = __ldg(&i2[lane + 32]);
    float2 c = __ldg(&i2[64]);
    bool skip = compute_skip(__shfl_sync(FULL, a.x, 0), __shfl_sync(FULL, a.y, 0),
                             __shfl_sync(FULL, b.y, 0), __shfl_sync(FULL, b.x, 1));
    float2* o2 = (float2*)(out + (size_t)frame * FRAME_LEN);
    if (skip) {
        __stcs(&o2[lane], a);
        __stcs(&o2[lane + 32], b);
        if (lane == 0) __stcs(&o2[64], c);
    } else {
        float bx_next = __shfl_down_sync(FULL, b.x, 1);
        float2 v0 = make_float2(b.y, (lane == 31) ? c.x : bx_next);
        float ay_prev = __shfl_up_sync(FULL, a.y, 1);
        float a0x     = __shfl_sync(FULL, a.x, 0);
        float2 v1 = (lane == 0) ? make_float2(c.y, a0x) : make_float2(ay_prev, a.x);
        float ay31 = __shfl_sync(FULL, a.y, 31);
        float b0x  = __shfl_sync(FULL, b.x, 0);
        __stcs(&o2[lane], v0);
        __stcs(&o2[lane + 32], v1);
        if (lane == 0) __stcs(&o2[64], make_float2(ay31, b0x));
    }
}

__global__ __launch_bounds__(512) void hand_sorter_v8(
    const float* __restrict__ X,
    float* __restrict__ out,
    int n_frames)
{
    const int gw = blockIdx.x * (blockDim.x >> 5) + (threadIdx.x >> 5);
    const int l  = threadIdx.x & 31;
    const int n_groups = n_frames >> 1;              // full 2-frame groups
    const int n_units  = n_groups + (n_frames & 1);
    if (gw >= n_units) return;
    if (gw == n_groups) {                            // odd tail frame
        tail_frame(X, out, n_frames - 1, l);
        return;
    }

    const float4* __restrict__ in4 = (const float4*)(X + (size_t)gw * 260);
    float4* __restrict__ o4        = (float4*)(out + (size_t)gw * 260);

    // Fully aligned 16B loads.
    float4 A = __ldg(&in4[l]);        // words 0..31   (frame A + elems 128..131 seam lives in B)
    float4 B = __ldg(&in4[l + 32]);   // words 32..63
    float4 C = __ldg(&in4[64]);      // word 64 (uniform)

    // Broadcasts used by predicates and seams.
    float ax0  = __shfl_sync(FULL, A.x, 0);
    float ay0  = __shfl_sync(FULL, A.y, 0);
    float ay16 = __shfl_sync(FULL, A.y, 16);   // elem 65
    float az16 = __shfl_sync(FULL, A.z, 16);   // elem 66
    float b0x  = __shfl_sync(FULL, B.x, 0);    // elem 128
    float b0y  = __shfl_sync(FULL, B.y, 0);    // elem 129
    float b0z  = __shfl_sync(FULL, B.z, 0);    // elem 130 (frame B h0)
    float b0w  = __shfl_sync(FULL, B.w, 0);    // elem 131 (frame B p0)
    float b16w = __shfl_sync(FULL, B.w, 16);   // elem 195 (frame B h1)
    float b17x = __shfl_sync(FULL, B.x, 17);   // elem 196 (frame B p1)

    bool skipA = compute_skip(ax0, ay0, ay16, az16);
    bool skipB = compute_skip(b0z, b0w, b16w, b17x);

    const int s1 = (l + 16) & 31;
    const int s2 = (l <= 15) ? ((l + 17) & 31) : ((l + 15) & 31);

    float4 W0, W1, W2;
    float fA128, fA129;   // out elems 128,129 (frame A part of seam word 32)
    float fB130, fB131;   // out elems 130,131 (frame B part of seam word 32)

    if (skipA) {
        W0 = A;
        fA128 = b0x;  fA129 = b0y;
    } else {
        // out word w (w=0..31) = in elems {(4w+65+k) mod 130}
        float Px = __shfl_sync(FULL, A.x, s1);
        float Py = __shfl_sync(FULL, A.y, s1);
        float Pz = __shfl_sync(FULL, A.z, s1);
        float Pw = __shfl_sync(FULL, A.w, s1);
        float qx = __shfl_sync(FULL, A.x, s2);
        float qw = __shfl_sync(FULL, A.w, s2);
        if (l <= 14)      W0 = make_float4(Py, Pz, Pw, qx);   // A[l+16].yzw, A[l+17].x
        else if (l == 15) W0 = make_float4(Py, Pz, Pw, b0x);  // ..., elem128
        else if (l == 16) W0 = make_float4(b0y, Px, Py, Pz);  // elem129, A[0].xyz
        else              W0 = make_float4(qw, Px, Py, Pz);   // A[l-17].w, A[l-16].xyz
        fA128 = __shfl_sync(FULL, A.w, 15);   // in elem 63
        fA129 = __shfl_sync(FULL, A.x, 16);   // in elem 64
    }

    if (skipB) {
        W1 = B;
        W2 = C;
        fB130 = b0z;  fB131 = b0w;
    } else {
        // frame B ring: out elem e (132..255): src = e+65 (e<195) else e-65
        float Px = __shfl_sync(FULL, B.x, s1);
        float Py = __shfl_sync(FULL, B.y, s1);
        float Pz = __shfl_sync(FULL, B.z, s1);
        float Pw = __shfl_sync(FULL, B.w, s1);
        float qx = __shfl_sync(FULL, B.x, s2);
        float qw = __shfl_sync(FULL, B.w, s2);
        if (l <= 14)      W1 = make_float4(Py, Pz, Pw, qx);   // B[l+16].yzw, B[l+17].x
        else if (l == 15) W1 = make_float4(Py, Pz, Pw, C.x);  // B[31].yzw, elem256
        else if (l == 16) W1 = make_float4(C.y, C.z, C.w, b0z); // elems 257..259, 130
        else              W1 = make_float4(qw, Px, Py, Pz);   // B[l-17].w, B[l-16].xyz
        float b15w = __shfl_sync(FULL, B.w, 15);  // in elem 191
        float b16x = __shfl_sync(FULL, B.x, 16);  // 192
        float b16y = __shfl_sync(FULL, B.y, 16);  // 193
        float b16z = __shfl_sync(FULL, B.z, 16);  // 194
        W2 = make_float4(b15w, b16x, b16y, b16z);
        fB130 = b16w;  fB131 = b17x;              // in elems 195,196
    }

    // Seam word 32 (lane 0 of W1) mixes both frames.
    if (l == 0) W1 = make_float4(fA128, fA129, fB130, fB131);

    __stcs(&o4[l], W0);
    __stcs(&o4[l + 32], W1);
    if (l == 0) __stcs(&o4[64], W2);
}

extern "C" void kernel_launch(void* const* d_in, const int* in_sizes, int n_in,
                              void* d_out, int out_size)
{
    const float* X = (const float*)d_in[0];
    // d_in[1] (swap_pattern int32[130]) is the fixed 65<->65 half swap; computed
    // analytically, so it isn't gathered.
    float* out = (float*)d_out;

    int n_frames = in_sizes[0] / FRAME_LEN;
    int n_units  = (n_frames + 1) >> 1;              // one warp per 2-frame group
    const int threads = 512;
    int warps_per_block = threads / 32;
    int blocks = (n_units + warps_per_block - 1) / warps_per_block;

    hand_sorter_v8<<<blocks, threads>>>(X, out, n_frames);
}

// round 9
// speedup vs baseline: 1.0477x; 1.0477x over previous
#include <cuda_runtime.h>

// Hand_Input_Sorter: per-frame conditional 65<->65 half-swap of [*,130] fp32.
// Final family (v7 shape): warp-per-frame (2 frames/warp), front-batched float2
// loads (default cache: frame-boundary sectors are reused by neighbor warps in
// L2), aligned float2 stores on BOTH paths (default policy; partial-line merge
// in L2), swap permutation realized with warp shuffles.

static constexpr int FRAME_LEN = 130;
static constexpr unsigned FULL = 0xFFFFFFFFu;

__device__ __forceinline__ bool compute_skip(float h0, float p0, float h1, float p1)
{
    bool nan0 = isnan(h0);
    bool nan1 = isnan(h1);
    bool skip = (h1 > h0);                 // false if either NaN (IEEE, matches jnp)
    skip |= (nan0 && nan1);                // both missing
    skip |= (nan0 && (h1 == 1.0f));        // only hand1, labeled right
    skip |= (nan1 && (h0 == 0.0f));        // only hand0, labeled left
    if (!nan0 && !nan1 && (h0 == h1)) {
        skip |= ((h0 == 0.0f) && (p0 > p1));
        skip |= ((h0 == 1.0f) && (p0 < p1));
    }
    return skip;
}

// Pairs: a = pair[lane] (elems 2l,2l+1), b = pair[lane+32] (elems 64+2l,65+2l),
// c = pair[64] (elems 128,129), loaded uniformly on all lanes.
__device__ __forceinline__ void store_frame(float* __restrict__ o, int lane,
                                            float2 a, float2 b, float2 c, bool skip)
{
    float2* __restrict__ o2 = (float2*)o;
    if (skip) {
        o2[lane]      = a;
        o2[lane + 32] = b;
        if (lane == 0) o2[64] = c;
    } else {
        // out[j] = X[j+65] (j<65) / X[j-65] (j>=65), as float2 slots:
        // slot lane:    {b.y, b[lane+1].x} with b[32] := c
        float bx_next = __shfl_down_sync(FULL, b.x, 1);
        float2 v0 = make_float2(b.y, (lane == 31) ? c.x : bx_next);
        // slot lane+32: lane0 -> {c.y, a[0].x}; else {a[lane-1].y, a.x}
        float ay_prev = __shfl_up_sync(FULL, a.y, 1);
        float a0x     = __shfl_sync(FULL, a.x, 0);
        float2 v1 = (lane == 0) ? make_float2(c.y, a0x)
                                : make_float2(ay_prev, a.x);
        // slot 64: {a[31].y, b[0].x}
        float ay31 = __shfl_sync(FULL, a.y, 31);
        float b0x  = __shfl_sync(FULL, b.x, 0);
        o2[lane]      = v0;
        o2[lane + 32] = v1;
        if (lane == 0) o2[64] = make_float2(ay31, b0x);
    }
}

__global__ __launch_bounds__(512) void hand_sorter_v9(
    const float* __restrict__ X,
    float* __restrict__ out,
    int n_frames)
{
    const int gw   = blockIdx.x * (blockDim.x >> 5) + (threadIdx.x >> 5);
    const int lane = threadIdx.x & 31;
    const int f0   = gw * 2;
    if (f0 >= n_frames) return;
    const bool has2 = (f0 + 1) < n_frames;

    const float2* __restrict__ i0 = (const float2*)(X + (size_t)f0 * FRAME_LEN);
    const float2* __restrict__ i1 = (const float2*)(X + (size_t)(f0 + 1) * FRAME_LEN);

    // Front-batch all loads; default cache policy.
    float2 a0 = __ldg(&i0[lane]);
    float2 b0 = __ldg(&i0[lane + 32]);
    float2 c0 = __ldg(&i0[64]);
    float2 a1 = make_float2(0.f, 0.f), b1 = a1, c1 = a1;
    if (has2) {
        a1 = __ldg(&i1[lane]);
        b1 = __ldg(&i1[lane + 32]);
        c1 = __ldg(&i1[64]);
    }

    // h0=a.x@0, p0=a.y@0, h1=elem65=b.y@0, p1=elem66=b.x@1
    bool skip0 = compute_skip(__shfl_sync(FULL, a0.x, 0), __shfl_sync(FULL, a0.y, 0),
                              __shfl_sync(FULL, b0.y, 0), __shfl_sync(FULL, b0.x, 1));
    bool skip1 = false;
    if (has2)
        skip1 = compute_skip(__shfl_sync(FULL, a1.x, 0), __shfl_sync(FULL, a1.y, 0),
                             __shfl_sync(FULL, b1.y, 0), __shfl_sync(FULL, b1.x, 1));

    store_frame(out + (size_t)f0 * FRAME_LEN, lane, a0, b0, c0, skip0);
    if (has2)
        store_frame(out + (size_t)(f0 + 1) * FRAME_LEN, lane, a1, b1, c1, skip1);
}

extern "C" void kernel_launch(void* const* d_in, const int* in_sizes, int n_in,
                              void* d_out, int out_size)
{
    const float* X = (const float*)d_in[0];
    // d_in[1] (swap_pattern int32[130]) is the fixed 65<->65 half swap; computed
    // analytically, so it isn't gathered.
    float* out = (float*)d_out;

    int n_frames = in_sizes[0] / FRAME_LEN;
    int n_warps  = (n_frames + 1) / 2;
    const int threads = 512;
    int warps_per_block = threads / 32;
    int blocks = (n_warps + warps_per_block - 1) / warps_per_block;

    hand_sorter_v9<<<blocks, threads>>>(X, out, n_frames);
}